// round 2
// baseline (speedup 1.0000x reference)
#include <cuda_runtime.h>
#include <cuda_bf16.h>
#include <math.h>

#define N_NODES 100000
#define D 128
#define RREL 3
#define E_EDGES 600000

// Scratch: static device globals (no allocation allowed).
__device__ float g_M[(size_t)N_NODES * D];       // per-relation GEMM output (reused)
__device__ float g_acc[(size_t)N_NODES * D];     // scatter accumulator
__device__ float g_deg[(size_t)2 * RREL * N_NODES]; // [2r]=deg_out_r, [2r+1]=deg_in_r

// ---------------------------------------------------------------------------
// Zero accumulator + degree arrays
// ---------------------------------------------------------------------------
__global__ __launch_bounds__(256) void zero_kernel() {
    const int na = (N_NODES * D) / 4;          // float4 count for acc
    const int nd = (2 * RREL * N_NODES) / 4;   // float4 count for deg
    int i = blockIdx.x * 256 + threadIdx.x;
    float4 z = make_float4(0.f, 0.f, 0.f, 0.f);
    if (i < na) {
        ((float4*)g_acc)[i] = z;
    } else {
        int j = i - na;
        if (j < nd) ((float4*)g_deg)[j] = z;
    }
}

// ---------------------------------------------------------------------------
// Degree counting: grid.y = relation
// ---------------------------------------------------------------------------
__global__ __launch_bounds__(256) void degree_kernel(
    const int* __restrict__ s0, const int* __restrict__ d0,
    const int* __restrict__ s1, const int* __restrict__ d1,
    const int* __restrict__ s2, const int* __restrict__ d2)
{
    int e = blockIdx.x * 256 + threadIdx.x;
    if (e >= E_EDGES) return;
    int r = blockIdx.y;
    const int* sp = (r == 0) ? s0 : ((r == 1) ? s1 : s2);
    const int* dp = (r == 0) ? d0 : ((r == 1) ? d1 : d2);
    atomicAdd(&g_deg[(size_t)(2 * r) * N_NODES + sp[e]], 1.0f);
    atomicAdd(&g_deg[(size_t)(2 * r + 1) * N_NODES + dp[e]], 1.0f);
}

// ---------------------------------------------------------------------------
// GEMM: M = X @ W   (X: [n,128] row-major, W: [128,128] row-major)
// 128x128 block tile, 256 threads, 8x8 register tile, K chunks of 32.
// ---------------------------------------------------------------------------
#define BM 128
#define BN 128
#define BK 32
#define TM 8
#define TN 8

__global__ __launch_bounds__(256) void gemm_kernel(
    const float* __restrict__ X, const float* __restrict__ W, int n)
{
    __shared__ float As[BK][BM + 4];  // As[k][m] (transposed X tile)
    __shared__ float Bs[BK][BN + 4];  // Bs[k][n]

    const int row0 = blockIdx.x * BM;
    const int tid = threadIdx.x;
    const int tx = tid & 15;          // 0..15 -> 8 output cols each
    const int ty = tid >> 4;          // 0..15 -> 8 output rows each

    float acc[TM][TN];
#pragma unroll
    for (int i = 0; i < TM; i++)
#pragma unroll
        for (int j = 0; j < TN; j++) acc[i][j] = 0.f;

    for (int kc = 0; kc < D; kc += BK) {
        // Load A tile (128 rows x 32 k) transposed into As[k][m]
#pragma unroll
        for (int i = 0; i < 4; i++) {
            int f = tid + i * 256;        // float4 index, 1024 total
            int m = f >> 3;               // 0..127
            int kq = (f & 7) * 4;         // 0,4,...,28
            int grow = row0 + m;
            float4 v = make_float4(0.f, 0.f, 0.f, 0.f);
            if (grow < n)
                v = *(const float4*)(X + (size_t)grow * D + kc + kq);
            As[kq + 0][m] = v.x;
            As[kq + 1][m] = v.y;
            As[kq + 2][m] = v.z;
            As[kq + 3][m] = v.w;
        }
        // Load B tile (32 k x 128 cols)
#pragma unroll
        for (int i = 0; i < 4; i++) {
            int f = tid + i * 256;
            int k = f >> 5;               // 0..31
            int nn = (f & 31) * 4;        // 0..124
            float4 v = *(const float4*)(W + (size_t)(kc + k) * D + nn);
            *(float4*)&Bs[k][nn] = v;
        }
        __syncthreads();

#pragma unroll
        for (int k = 0; k < BK; k++) {
            float a[TM], b[TN];
#pragma unroll
            for (int i = 0; i < TM; i++) a[i] = As[k][ty * TM + i];
#pragma unroll
            for (int j = 0; j < TN; j++) b[j] = Bs[k][tx * TN + j];
#pragma unroll
            for (int i = 0; i < TM; i++)
#pragma unroll
                for (int j = 0; j < TN; j++)
                    acc[i][j] = fmaf(a[i], b[j], acc[i][j]);
        }
        __syncthreads();
    }

#pragma unroll
    for (int i = 0; i < TM; i++) {
        int grow = row0 + ty * TM + i;
        if (grow < n) {
#pragma unroll
            for (int j = 0; j < TN; j += 4) {
                float4 v = make_float4(acc[i][j], acc[i][j + 1],
                                       acc[i][j + 2], acc[i][j + 3]);
                *(float4*)(g_M + (size_t)grow * D + tx * TN + j) = v;
            }
        }
    }
}

// ---------------------------------------------------------------------------
// Scatter: acc[dst] += rsqrt(deg_out[src]) * rsqrt(deg_in[dst]) * M[src]
// One warp per edge, 128-bit vector atomics (sm_90+).
// ---------------------------------------------------------------------------
__global__ __launch_bounds__(256) void scatter_kernel(
    const int* __restrict__ src, const int* __restrict__ dst, int r)
{
    int w = (blockIdx.x * 256 + threadIdx.x) >> 5;
    if (w >= E_EDGES) return;
    int lane = threadIdx.x & 31;

    int s = __ldg(src + w);
    int d = __ldg(dst + w);
    float dout = g_deg[(size_t)(2 * r) * N_NODES + s];
    float din  = g_deg[(size_t)(2 * r + 1) * N_NODES + d];
    float c = rsqrtf(fmaxf(dout, 1.0f)) * rsqrtf(fmaxf(din, 1.0f));

    float4 v = *(const float4*)(g_M + (size_t)s * D + lane * 4);
    v.x *= c; v.y *= c; v.z *= c; v.w *= c;

    atomicAdd((float4*)(g_acc + (size_t)d * D + lane * 4), v);
}

// ---------------------------------------------------------------------------
// Epilogue: out = relu(acc + b0 + b1 + b2)
// ---------------------------------------------------------------------------
__global__ __launch_bounds__(256) void epilogue_kernel(
    const float* __restrict__ b0, const float* __restrict__ b1,
    const float* __restrict__ b2, float* __restrict__ out)
{
    int i = blockIdx.x * 256 + threadIdx.x;   // float4 index
    const int total4 = (N_NODES * D) / 4;
    if (i >= total4) return;
    int col = (i & 31) * 4;                   // column of first component
    float4 a = ((const float4*)g_acc)[i];
    float4 b;
    b.x = b0[col + 0] + b1[col + 0] + b2[col + 0];
    b.y = b0[col + 1] + b1[col + 1] + b2[col + 1];
    b.z = b0[col + 2] + b1[col + 2] + b2[col + 2];
    b.w = b0[col + 3] + b1[col + 3] + b2[col + 3];
    float4 o;
    o.x = fmaxf(a.x + b.x, 0.f);
    o.y = fmaxf(a.y + b.y, 0.f);
    o.z = fmaxf(a.z + b.z, 0.f);
    o.w = fmaxf(a.w + b.w, 0.f);
    ((float4*)out)[i] = o;
}

// ---------------------------------------------------------------------------
// Launcher: classify inputs by element count (robust to metadata ordering).
// ---------------------------------------------------------------------------
extern "C" void kernel_launch(void* const* d_in, const int* in_sizes, int n_in,
                              void* d_out, int out_size)
{
    const float* x = nullptr;
    const float* Wp[RREL] = {nullptr, nullptr, nullptr};
    const float* bp[RREL] = {nullptr, nullptr, nullptr};
    const int*   ep[2 * RREL] = {nullptr};  // src0,dst0,src1,dst1,src2,dst2
    int wi = 0, bi = 0, ei = 0;

    for (int i = 0; i < n_in; i++) {
        int sz = in_sizes[i];
        if (sz == N_NODES * D)      x = (const float*)d_in[i];
        else if (sz == D * D)       { if (wi < RREL) Wp[wi++] = (const float*)d_in[i]; }
        else if (sz == D)           { if (bi < RREL) bp[bi++] = (const float*)d_in[i]; }
        else if (sz == E_EDGES)     { if (ei < 2 * RREL) ep[ei++] = (const int*)d_in[i]; }
    }

    float* out = (float*)d_out;

    // 1. zero acc + degree arrays
    {
        int total = (N_NODES * D) / 4 + (2 * RREL * N_NODES) / 4;
        int blocks = (total + 255) / 256;
        zero_kernel<<<blocks, 256>>>();
    }

    // 2. degrees (all relations)
    {
        dim3 grid((E_EDGES + 255) / 256, RREL);
        degree_kernel<<<grid, 256>>>(ep[0], ep[1], ep[2], ep[3], ep[4], ep[5]);
    }

    // 3. per relation: GEMM then scatter (keeps M_r + acc hot in L2)
    const int gemm_blocks = (N_NODES + BM - 1) / BM;
    const int scat_blocks = ((long long)E_EDGES * 32 + 255) / 256;
    for (int r = 0; r < RREL; r++) {
        gemm_kernel<<<gemm_blocks, 256>>>(x, Wp[r], N_NODES);
        scatter_kernel<<<scat_blocks, 256>>>(ep[2 * r], ep[2 * r + 1], r);
    }

    // 4. epilogue: bias + relu
    {
        int total4 = (N_NODES * D) / 4;
        epilogue_kernel<<<(total4 + 255) / 256, 256>>>(bp[0], bp[1], bp[2], out);
    }
}

// round 5
// speedup vs baseline: 1.2058x; 1.2058x over previous
#include <cuda_runtime.h>
#include <cuda_bf16.h>
#include <cstdint>
#include <math.h>

#define N_NODES 100000
#define D 128
#define RREL 3
#define E_EDGES 600000
#define TILES ((N_NODES + 127) / 128)   // 782
#define NM ((size_t)N_NODES * D)

// Scratch: static device globals (no allocation allowed).
__device__ float g_M[RREL * NM];                    // per-relation GEMM outputs
__device__ float g_acc[NM];                         // scatter accumulator
__device__ float g_deg[(size_t)2 * RREL * N_NODES]; // [2r]=deg_out_r, [2r+1]=deg_in_r
__device__ uint32_t g_Bh[RREL * 8192];              // W_r^T bf16 hi, row-major [n][k] (32KB/rel)
__device__ uint32_t g_Bl[RREL * 8192];              // W_r^T bf16 lo

// ---------------------------------------------------------------------------
// Helpers
// ---------------------------------------------------------------------------
__device__ __forceinline__ uint32_t smem_u32(const void* p) {
    uint32_t a;
    asm("{ .reg .u64 t; cvta.to.shared.u64 t, %1; cvt.u32.u64 %0, t; }"
        : "=r"(a) : "l"(p));
    return a;
}

__device__ __forceinline__ void ldm4(uint32_t r[4], uint32_t addr) {
    asm volatile("ldmatrix.sync.aligned.m8n8.x4.shared.b16 {%0,%1,%2,%3}, [%4];"
                 : "=r"(r[0]), "=r"(r[1]), "=r"(r[2]), "=r"(r[3]) : "r"(addr));
}

__device__ __forceinline__ void mma_bf16(float c[4], const uint32_t a[4],
                                         uint32_t b0, uint32_t b1) {
    asm volatile(
        "mma.sync.aligned.m16n8k16.row.col.f32.bf16.bf16.f32 "
        "{%0,%1,%2,%3}, {%4,%5,%6,%7}, {%8,%9}, {%0,%1,%2,%3};"
        : "+f"(c[0]), "+f"(c[1]), "+f"(c[2]), "+f"(c[3])
        : "r"(a[0]), "r"(a[1]), "r"(a[2]), "r"(a[3]), "r"(b0), "r"(b1));
}

// ---------------------------------------------------------------------------
// Zero accumulator + degree arrays
// ---------------------------------------------------------------------------
__global__ __launch_bounds__(256) void zero_kernel() {
    const int na = (N_NODES * D) / 4;
    const int nd = (2 * RREL * N_NODES) / 4;
    int i = blockIdx.x * 256 + threadIdx.x;
    float4 z = make_float4(0.f, 0.f, 0.f, 0.f);
    if (i < na) {
        ((float4*)g_acc)[i] = z;
    } else {
        int j = i - na;
        if (j < nd) ((float4*)g_deg)[j] = z;
    }
}

// ---------------------------------------------------------------------------
// Degree counting
// ---------------------------------------------------------------------------
__global__ __launch_bounds__(256) void degree_kernel(
    const int* __restrict__ s0, const int* __restrict__ d0,
    const int* __restrict__ s1, const int* __restrict__ d1,
    const int* __restrict__ s2, const int* __restrict__ d2)
{
    int e = blockIdx.x * 256 + threadIdx.x;
    if (e >= E_EDGES) return;
    int r = blockIdx.y;
    const int* sp = (r == 0) ? s0 : ((r == 1) ? s1 : s2);
    const int* dp = (r == 0) ? d0 : ((r == 1) ? d1 : d2);
    atomicAdd(&g_deg[(size_t)(2 * r) * N_NODES + sp[e]], 1.0f);
    atomicAdd(&g_deg[(size_t)(2 * r + 1) * N_NODES + dp[e]], 1.0f);
}

// ---------------------------------------------------------------------------
// Convert W_r -> transposed bf16 hi/lo, row-major [n][k]. blockIdx.x = rel.
// ---------------------------------------------------------------------------
__global__ __launch_bounds__(128) void convert_w_kernel(
    const float* __restrict__ W0, const float* __restrict__ W1,
    const float* __restrict__ W2)
{
    int r = blockIdx.x;
    const float* W = (r == 0) ? W0 : ((r == 1) ? W1 : W2);
    int n = threadIdx.x;  // output column = B row
    __nv_bfloat16* bh = (__nv_bfloat16*)(g_Bh + (size_t)r * 8192);
    __nv_bfloat16* bl = (__nv_bfloat16*)(g_Bl + (size_t)r * 8192);
#pragma unroll 4
    for (int k = 0; k < D; k++) {
        float w = W[(size_t)k * D + n];
        __nv_bfloat16 h = __float2bfloat16(w);
        __nv_bfloat16 l = __float2bfloat16(w - __bfloat162float(h));
        bh[n * D + k] = h;
        bl[n * D + k] = l;
    }
}

// ---------------------------------------------------------------------------
// HMMA GEMM, all 3 relations: M_r = Xh@Bh_r^T + Xh@Bl_r^T + Xl@Bh_r^T
// CTA = 128 rows x 128 cols, 256 threads (8 warps, warp tile 32x64).
// Smem tiles: 128 rows x 256B, 16B chunks XOR-swizzled by (row&7).
// ---------------------------------------------------------------------------
__global__ __launch_bounds__(256, 1) void gemm_hmma_kernel(const float* __restrict__ X)
{
    extern __shared__ char sm[];
    // layout: Xh[32K] Xl[32K] Bh[32K] Bl[32K]
    uint32_t sbase = smem_u32(sm);
    const uint32_t sXh = sbase;
    const uint32_t sXl = sbase + 32768;
    const uint32_t sBh = sbase + 65536;
    const uint32_t sBl = sbase + 98304;

    const int tid = threadIdx.x;
    const int wid = tid >> 5;
    const int lane = tid & 31;

    // ---- load X rows, convert to bf16 hi/lo into swizzled smem ----
    {
        int row = tid >> 1;                 // 0..127
        int half = tid & 1;                 // 0..1 (64 cols each)
        int grow = blockIdx.x * 128 + row;
        bool valid = grow < N_NODES;
        const float4* xr = (const float4*)(X + (size_t)(valid ? grow : 0) * D);
        uint32_t rowoff = (uint32_t)row * 256u;
        uint32_t rsw = (uint32_t)(row & 7) << 4;
#pragma unroll
        for (int i = 0; i < 8; i++) {
            int colbase = half * 64 + i * 8;          // 8 floats
            float4 v0 = make_float4(0.f, 0.f, 0.f, 0.f), v1 = v0;
            if (valid) {
                v0 = xr[colbase / 4];
                v1 = xr[colbase / 4 + 1];
            }
            float f[8] = {v0.x, v0.y, v0.z, v0.w, v1.x, v1.y, v1.z, v1.w};
            uint32_t hi[4], lo[4];
#pragma unroll
            for (int q = 0; q < 4; q++) {
                __nv_bfloat16 h0 = __float2bfloat16(f[q * 2]);
                __nv_bfloat16 h1 = __float2bfloat16(f[q * 2 + 1]);
                __nv_bfloat16 l0 = __float2bfloat16(f[q * 2] - __bfloat162float(h0));
                __nv_bfloat16 l1 = __float2bfloat16(f[q * 2 + 1] - __bfloat162float(h1));
                __nv_bfloat162 ph = {h0, h1}, pl = {l0, l1};
                hi[q] = *(uint32_t*)&ph;
                lo[q] = *(uint32_t*)&pl;
            }
            uint32_t chunk = (uint32_t)(colbase >> 3) << 4;   // 16B chunk byte off
            uint32_t off = rowoff + (chunk ^ rsw);
            asm volatile("st.shared.v4.b32 [%0], {%1,%2,%3,%4};"
                         :: "r"(sXh + off), "r"(hi[0]), "r"(hi[1]), "r"(hi[2]), "r"(hi[3]));
            asm volatile("st.shared.v4.b32 [%0], {%1,%2,%3,%4};"
                         :: "r"(sXl + off), "r"(lo[0]), "r"(lo[1]), "r"(lo[2]), "r"(lo[3]));
        }
    }

    // ---- warp tiling ----
    const int wm = wid & 3;           // 4 M-groups of 32 rows
    const int wn = wid >> 2;          // 2 N-groups of 64 cols
    const int m0 = wm * 32;
    const int n0 = wn * 64;

    // ldmatrix per-thread addressing (shared across A and B):
    const int t7 = lane & 7;
    const uint32_t dkc = (uint32_t)(lane >> 4);          // 0 or 1 (k+8 chunk)
    const int rsel = ((lane >> 3) & 1) * 8;              // row +8 within 16-tile
    const uint32_t aRowBase = (uint32_t)(m0 + t7 + rsel) * 256u;
    const uint32_t bRowBase = (uint32_t)(n0 + t7 + rsel) * 256u;
    const uint32_t rsw = (uint32_t)t7;                   // swizzle key

    const int gm0 = blockIdx.x * 128 + m0;

    // copy B tiles for a relation into smem (swizzled)
    auto copyB = [&](int r) {
        const uint4* srcH = (const uint4*)(g_Bh + (size_t)r * 8192);
        const uint4* srcL = (const uint4*)(g_Bl + (size_t)r * 8192);
#pragma unroll
        for (int j = 0; j < 8; j++) {
            int f = tid + j * 256;            // uint4 index, 2048 total
            uint32_t row = (uint32_t)(f >> 4);
            uint32_t chunk = (uint32_t)(f & 15);
            uint32_t off = row * 256u + ((chunk ^ (row & 7)) << 4);
            uint4 vh = srcH[f];
            uint4 vl = srcL[f];
            asm volatile("st.shared.v4.b32 [%0], {%1,%2,%3,%4};"
                         :: "r"(sBh + off), "r"(vh.x), "r"(vh.y), "r"(vh.z), "r"(vh.w));
            asm volatile("st.shared.v4.b32 [%0], {%1,%2,%3,%4};"
                         :: "r"(sBl + off), "r"(vl.x), "r"(vl.y), "r"(vl.z), "r"(vl.w));
        }
    };

    copyB(0);
    __syncthreads();

#pragma unroll 1
    for (int r = 0; r < RREL; r++) {
        if (r > 0) {
            __syncthreads();
            copyB(r);
            __syncthreads();
        }

        float C[2][8][4];
#pragma unroll
        for (int mi = 0; mi < 2; mi++)
#pragma unroll
            for (int nj = 0; nj < 8; nj++)
#pragma unroll
                for (int q = 0; q < 4; q++) C[mi][nj][q] = 0.f;

#pragma unroll
        for (int kk = 0; kk < 8; kk++) {
            uint32_t chunk = (((uint32_t)(kk * 2) + dkc) ^ rsw) << 4;
            uint32_t ah[8], al[8], bh[16], bl[16];
            ldm4(ah + 0, sXh + aRowBase + chunk);
            ldm4(ah + 4, sXh + aRowBase + 4096 + chunk);
            ldm4(al + 0, sXl + aRowBase + chunk);
            ldm4(al + 4, sXl + aRowBase + 4096 + chunk);
#pragma unroll
            for (int p = 0; p < 4; p++) {
                ldm4(bh + 4 * p, sBh + bRowBase + (uint32_t)p * 4096 + chunk);
                ldm4(bl + 4 * p, sBl + bRowBase + (uint32_t)p * 4096 + chunk);
            }
#pragma unroll
            for (int mi = 0; mi < 2; mi++) {
#pragma unroll
                for (int p = 0; p < 4; p++) {
                    // x4 output: r0=b0(n=16p), r1=b0(n=16p+8), r2=b1(16p), r3=b1(16p+8)
                    mma_bf16(C[mi][2 * p], ah + mi * 4, bh[4 * p], bh[4 * p + 2]);
                    mma_bf16(C[mi][2 * p + 1], ah + mi * 4, bh[4 * p + 1], bh[4 * p + 3]);
                    mma_bf16(C[mi][2 * p], ah + mi * 4, bl[4 * p], bl[4 * p + 2]);
                    mma_bf16(C[mi][2 * p + 1], ah + mi * 4, bl[4 * p + 1], bl[4 * p + 3]);
                    mma_bf16(C[mi][2 * p], al + mi * 4, bh[4 * p], bh[4 * p + 2]);
                    mma_bf16(C[mi][2 * p + 1], al + mi * 4, bh[4 * p + 1], bh[4 * p + 3]);
                }
            }
        }

        // store C -> g_M[r]
        float* Mr = g_M + (size_t)r * NM;
#pragma unroll
        for (int mi = 0; mi < 2; mi++) {
            int row0 = gm0 + mi * 16 + (lane >> 2);
            int row1 = row0 + 8;
#pragma unroll
            for (int nj = 0; nj < 8; nj++) {
                int col = n0 + nj * 8 + (lane & 3) * 2;
                if (row0 < N_NODES) {
                    float2 v = {C[mi][nj][0], C[mi][nj][1]};
                    *(float2*)(Mr + (size_t)row0 * D + col) = v;
                }
                if (row1 < N_NODES) {
                    float2 v = {C[mi][nj][2], C[mi][nj][3]};
                    *(float2*)(Mr + (size_t)row1 * D + col) = v;
                }
            }
        }
    }
}

// ---------------------------------------------------------------------------
// Scatter (all relations): acc[dst] += c_e * M_r[src] ;  grid.y = relation
// ---------------------------------------------------------------------------
__global__ __launch_bounds__(256) void scatter_kernel(
    const int* __restrict__ s0, const int* __restrict__ d0,
    const int* __restrict__ s1, const int* __restrict__ d1,
    const int* __restrict__ s2, const int* __restrict__ d2)
{
    int w = (blockIdx.x * 256 + threadIdx.x) >> 5;
    if (w >= E_EDGES) return;
    int lane = threadIdx.x & 31;
    int r = blockIdx.y;
    const int* src = (r == 0) ? s0 : ((r == 1) ? s1 : s2);
    const int* dst = (r == 0) ? d0 : ((r == 1) ? d1 : d2);
    const float* Mr = g_M + (size_t)r * NM;

    int s = __ldg(src + w);
    int d = __ldg(dst + w);
    float dout = g_deg[(size_t)(2 * r) * N_NODES + s];
    float din  = g_deg[(size_t)(2 * r + 1) * N_NODES + d];
    float c = rsqrtf(fmaxf(dout, 1.0f)) * rsqrtf(fmaxf(din, 1.0f));

    float4 v = *(const float4*)(Mr + (size_t)s * D + lane * 4);
    v.x *= c; v.y *= c; v.z *= c; v.w *= c;

    atomicAdd((float4*)(g_acc + (size_t)d * D + lane * 4), v);
}

// ---------------------------------------------------------------------------
// Epilogue: out = relu(acc + b0 + b1 + b2)
// ---------------------------------------------------------------------------
__global__ __launch_bounds__(256) void epilogue_kernel(
    const float* __restrict__ b0, const float* __restrict__ b1,
    const float* __restrict__ b2, float* __restrict__ out)
{
    int i = blockIdx.x * 256 + threadIdx.x;
    const int total4 = (N_NODES * D) / 4;
    if (i >= total4) return;
    int col = (i & 31) * 4;
    float4 a = ((const float4*)g_acc)[i];
    float4 b;
    b.x = b0[col + 0] + b1[col + 0] + b2[col + 0];
    b.y = b0[col + 1] + b1[col + 1] + b2[col + 1];
    b.z = b0[col + 2] + b1[col + 2] + b2[col + 2];
    b.w = b0[col + 3] + b1[col + 3] + b2[col + 3];
    float4 o;
    o.x = fmaxf(a.x + b.x, 0.f);
    o.y = fmaxf(a.y + b.y, 0.f);
    o.z = fmaxf(a.z + b.z, 0.f);
    o.w = fmaxf(a.w + b.w, 0.f);
    ((float4*)out)[i] = o;
}

// ---------------------------------------------------------------------------
// Launcher
// ---------------------------------------------------------------------------
extern "C" void kernel_launch(void* const* d_in, const int* in_sizes, int n_in,
                              void* d_out, int out_size)
{
    const float* x = nullptr;
    const float* Wp[RREL] = {nullptr, nullptr, nullptr};
    const float* bp[RREL] = {nullptr, nullptr, nullptr};
    const int*   ep[2 * RREL] = {nullptr};
    int wi = 0, bi = 0, ei = 0;

    for (int i = 0; i < n_in; i++) {
        int sz = in_sizes[i];
        if (sz == N_NODES * D)      x = (const float*)d_in[i];
        else if (sz == D * D)       { if (wi < RREL) Wp[wi++] = (const float*)d_in[i]; }
        else if (sz == D)           { if (bi < RREL) bp[bi++] = (const float*)d_in[i]; }
        else if (sz == E_EDGES)     { if (ei < 2 * RREL) ep[ei++] = (const int*)d_in[i]; }
    }

    float* out = (float*)d_out;
    const int GEMM_SMEM = 4 * 32768;  // 128KB
    cudaFuncSetAttribute(gemm_hmma_kernel,
                         cudaFuncAttributeMaxDynamicSharedMemorySize, GEMM_SMEM);

    // 1. zero acc + degree arrays
    {
        int total = (N_NODES * D) / 4 + (2 * RREL * N_NODES) / 4;
        zero_kernel<<<(total + 255) / 256, 256>>>();
    }

    // 2. degrees
    {
        dim3 grid((E_EDGES + 255) / 256, RREL);
        degree_kernel<<<grid, 256>>>(ep[0], ep[1], ep[2], ep[3], ep[4], ep[5]);
    }

    // 3. convert W to transposed bf16 hi/lo
    convert_w_kernel<<<RREL, 128>>>(Wp[0], Wp[1], Wp[2]);

    // 4. tensor-core GEMM, all relations
    gemm_hmma_kernel<<<TILES, 256, GEMM_SMEM>>>(x);

    // 5. scatter, all relations
    {
        dim3 grid((unsigned)(((long long)E_EDGES * 32 + 255) / 256), RREL);
        scatter_kernel<<<grid, 256>>>(ep[0], ep[1], ep[2], ep[3], ep[4], ep[5]);
    }

    // 6. epilogue
    {
        int total4 = (N_NODES * D) / 4;
        epilogue_kernel<<<(total4 + 255) / 256, 256>>>(bp[0], bp[1], bp[2], out);
    }
}

// round 6
// speedup vs baseline: 1.6103x; 1.3355x over previous
#include <cuda_runtime.h>
#include <cuda_bf16.h>
#include <cstdint>
#include <math.h>

#define N_NODES 100000
#define D 128
#define RREL 3
#define E_EDGES 600000
#define TILES64 ((N_NODES + 63) / 64)   // 1563
#define NM ((size_t)N_NODES * D)
#define TOT3N (3 * N_NODES)

// Scratch: static device globals (no allocation allowed).
__device__ float    g_M[RREL * NM];                    // per-relation GEMM outputs
__device__ float    g_deg[(size_t)2 * RREL * N_NODES]; // [2r]=deg_out_r, [2r+1]=deg_in_r
__device__ uint32_t g_Bh[RREL * 8192];                 // W_r^T bf16 hi, [n][k] (32KB/rel)
__device__ uint32_t g_Bl[RREL * 8192];                 // W_r^T bf16 lo
__device__ int      g_off[TOT3N + 1];                  // CSR offsets (concat over relations)
__device__ int      g_cursor[TOT3N];                   // fill cursors
__device__ int      g_blk[512];                        // scan block sums
__device__ uint2    g_edges[RREL * E_EDGES];           // {src, coef} CSR by dst
__device__ float    g_bsum[D];                         // b0+b1+b2

// ---------------------------------------------------------------------------
// Helpers
// ---------------------------------------------------------------------------
__device__ __forceinline__ uint32_t smem_u32(const void* p) {
    uint32_t a;
    asm("{ .reg .u64 t; cvta.to.shared.u64 t, %1; cvt.u32.u64 %0, t; }"
        : "=r"(a) : "l"(p));
    return a;
}

__device__ __forceinline__ void ldm4(uint32_t r[4], uint32_t addr) {
    asm volatile("ldmatrix.sync.aligned.m8n8.x4.shared.b16 {%0,%1,%2,%3}, [%4];"
                 : "=r"(r[0]), "=r"(r[1]), "=r"(r[2]), "=r"(r[3]) : "r"(addr));
}

__device__ __forceinline__ void mma_bf16(float c[4], const uint32_t a[4],
                                         uint32_t b0, uint32_t b1) {
    asm volatile(
        "mma.sync.aligned.m16n8k16.row.col.f32.bf16.bf16.f32 "
        "{%0,%1,%2,%3}, {%4,%5,%6,%7}, {%8,%9}, {%0,%1,%2,%3};"
        : "+f"(c[0]), "+f"(c[1]), "+f"(c[2]), "+f"(c[3])
        : "r"(a[0]), "r"(a[1]), "r"(a[2]), "r"(a[3]), "r"(b0), "r"(b1));
}

// ---------------------------------------------------------------------------
// Zero: degrees (600000 floats) + cursors (300000 ints)
// ---------------------------------------------------------------------------
__global__ __launch_bounds__(256) void zero_kernel() {
    const int nf4 = (2 * RREL * N_NODES) / 4;   // 150000
    const int ni4 = TOT3N / 4;                  // 75000
    int i = blockIdx.x * 256 + threadIdx.x;
    if (i < nf4) {
        ((float4*)g_deg)[i] = make_float4(0.f, 0.f, 0.f, 0.f);
    } else {
        int j = i - nf4;
        if (j < ni4) ((int4*)g_cursor)[j] = make_int4(0, 0, 0, 0);
    }
}

// ---------------------------------------------------------------------------
// Degree counting
// ---------------------------------------------------------------------------
__global__ __launch_bounds__(256) void degree_kernel(
    const int* __restrict__ s0, const int* __restrict__ d0,
    const int* __restrict__ s1, const int* __restrict__ d1,
    const int* __restrict__ s2, const int* __restrict__ d2)
{
    int e = blockIdx.x * 256 + threadIdx.x;
    if (e >= E_EDGES) return;
    int r = blockIdx.y;
    const int* sp = (r == 0) ? s0 : ((r == 1) ? s1 : s2);
    const int* dp = (r == 0) ? d0 : ((r == 1) ? d1 : d2);
    atomicAdd(&g_deg[(size_t)(2 * r) * N_NODES + sp[e]], 1.0f);
    atomicAdd(&g_deg[(size_t)(2 * r + 1) * N_NODES + dp[e]], 1.0f);
}

// ---------------------------------------------------------------------------
// Convert W_r -> transposed bf16 hi/lo, row-major [n][k]; also bias sum.
// ---------------------------------------------------------------------------
__global__ __launch_bounds__(128) void convert_w_kernel(
    const float* __restrict__ W0, const float* __restrict__ W1,
    const float* __restrict__ W2,
    const float* __restrict__ b0, const float* __restrict__ b1,
    const float* __restrict__ b2)
{
    int r = blockIdx.x;
    const float* W = (r == 0) ? W0 : ((r == 1) ? W1 : W2);
    int n = threadIdx.x;
    if (r == 0) g_bsum[n] = b0[n] + b1[n] + b2[n];
    __nv_bfloat16* bh = (__nv_bfloat16*)(g_Bh + (size_t)r * 8192);
    __nv_bfloat16* bl = (__nv_bfloat16*)(g_Bl + (size_t)r * 8192);
#pragma unroll 4
    for (int k = 0; k < D; k++) {
        float w = W[(size_t)k * D + n];
        __nv_bfloat16 h = __float2bfloat16(w);
        __nv_bfloat16 l = __float2bfloat16(w - __bfloat162float(h));
        bh[n * D + k] = h;
        bl[n * D + k] = l;
    }
}

// ---------------------------------------------------------------------------
// Scan pass 1: per-block (1024 elems) exclusive scan of concatenated deg_in
// ---------------------------------------------------------------------------
__global__ __launch_bounds__(256) void scan1_kernel() {
    __shared__ int warpsum[8];
    int tid = threadIdx.x;
    int base = blockIdx.x * 1024 + tid * 4;
    int v[4];
#pragma unroll
    for (int j = 0; j < 4; j++) {
        int idx = base + j;
        int val = 0;
        if (idx < TOT3N) {
            int r = idx / N_NODES;
            int i = idx - r * N_NODES;
            val = (int)(g_deg[(size_t)(2 * r + 1) * N_NODES + i] + 0.5f);
        }
        v[j] = val;
    }
    int s = v[0] + v[1] + v[2] + v[3];
    int lane = tid & 31, wid = tid >> 5;
    int inc = s;
#pragma unroll
    for (int dlt = 1; dlt < 32; dlt <<= 1) {
        int t = __shfl_up_sync(0xffffffffu, inc, dlt);
        if (lane >= dlt) inc += t;
    }
    if (lane == 31) warpsum[wid] = inc;
    __syncthreads();
    if (wid == 0) {
        int ws = (lane < 8) ? warpsum[lane] : 0;
#pragma unroll
        for (int dlt = 1; dlt < 8; dlt <<= 1) {
            int t = __shfl_up_sync(0xffffffffu, ws, dlt);
            if (lane >= dlt) ws += t;
        }
        if (lane < 8) warpsum[lane] = ws;
    }
    __syncthreads();
    int warpbase = (wid > 0) ? warpsum[wid - 1] : 0;
    int run = warpbase + inc - s;
#pragma unroll
    for (int j = 0; j < 4; j++) {
        int idx = base + j;
        if (idx < TOT3N) g_off[idx] = run;
        run += v[j];
    }
    if (tid == 255) g_blk[blockIdx.x] = warpsum[7];
}

// ---------------------------------------------------------------------------
// Scan pass 2: exclusive scan of block sums (nblk <= 512), single block
// ---------------------------------------------------------------------------
__global__ __launch_bounds__(512) void scan2_kernel(int nblk) {
    __shared__ int sh[512];
    int tid = threadIdx.x;
    sh[tid] = (tid < nblk) ? g_blk[tid] : 0;
    __syncthreads();
#pragma unroll
    for (int dlt = 1; dlt < 512; dlt <<= 1) {
        int t = (tid >= dlt) ? sh[tid - dlt] : 0;
        __syncthreads();
        sh[tid] += t;
        __syncthreads();
    }
    if (tid < nblk) g_blk[tid] = (tid > 0) ? sh[tid - 1] : 0;
    if (tid == 0) g_off[TOT3N] = sh[511];
}

// ---------------------------------------------------------------------------
// Scan pass 3: add block offsets
// ---------------------------------------------------------------------------
__global__ __launch_bounds__(256) void scan3_kernel() {
    int i = blockIdx.x * 256 + threadIdx.x;
    if (i < TOT3N) g_off[i] += g_blk[i >> 10];
}

// ---------------------------------------------------------------------------
// Fill CSR edge lists: g_edges[pos] = {src, c_e}, sorted by (rel, dst)
// ---------------------------------------------------------------------------
__global__ __launch_bounds__(256) void fill_kernel(
    const int* __restrict__ s0, const int* __restrict__ d0,
    const int* __restrict__ s1, const int* __restrict__ d1,
    const int* __restrict__ s2, const int* __restrict__ d2)
{
    int e = blockIdx.x * 256 + threadIdx.x;
    if (e >= E_EDGES) return;
    int r = blockIdx.y;
    const int* sp = (r == 0) ? s0 : ((r == 1) ? s1 : s2);
    const int* dp = (r == 0) ? d0 : ((r == 1) ? d1 : d2);
    int s = __ldg(sp + e);
    int d = __ldg(dp + e);
    float dout = g_deg[(size_t)(2 * r) * N_NODES + s];
    float din  = g_deg[(size_t)(2 * r + 1) * N_NODES + d];
    float c = rsqrtf(fmaxf(dout, 1.0f)) * rsqrtf(fmaxf(din, 1.0f));
    int idx = r * N_NODES + d;
    int pos = g_off[idx] + atomicAdd(&g_cursor[idx], 1);
    g_edges[pos] = make_uint2((uint32_t)s, __float_as_uint(c));
}

// ---------------------------------------------------------------------------
// HMMA GEMM, all 3 relations: M_r = Xh@Bh_r^T + Xh@Bl_r^T + Xl@Bh_r^T
// CTA = 64 rows x 128 cols, 256 threads (8 warps, warp tile 16x64), 96KB smem
// -> 2 CTAs/SM. Smem rows 256B, 16B chunks XOR-swizzled by (row&7).
// ---------------------------------------------------------------------------
__global__ __launch_bounds__(256, 2) void gemm_hmma_kernel(const float* __restrict__ X)
{
    extern __shared__ char sm[];
    uint32_t sbase = smem_u32(sm);
    const uint32_t sXh = sbase;             // 16KB (64 rows x 256B)
    const uint32_t sXl = sbase + 16384;
    const uint32_t sBh = sbase + 32768;     // 32KB (128 rows x 256B)
    const uint32_t sBl = sbase + 65536;

    const int tid = threadIdx.x;
    const int wid = tid >> 5;
    const int lane = tid & 31;

    // ---- load X rows (64), convert to bf16 hi/lo into swizzled smem ----
    {
        int row = tid >> 2;                 // 0..63
        int q = tid & 3;                    // 32-col quarter
        int grow = blockIdx.x * 64 + row;
        bool valid = grow < N_NODES;
        const float4* xr = (const float4*)(X + (size_t)(valid ? grow : 0) * D);
        uint32_t rowoff = (uint32_t)row * 256u;
        uint32_t rsw = (uint32_t)(row & 7) << 4;
#pragma unroll
        for (int i = 0; i < 4; i++) {
            int colbase = q * 32 + i * 8;
            float4 v0 = make_float4(0.f, 0.f, 0.f, 0.f), v1 = v0;
            if (valid) {
                v0 = xr[colbase / 4];
                v1 = xr[colbase / 4 + 1];
            }
            float f[8] = {v0.x, v0.y, v0.z, v0.w, v1.x, v1.y, v1.z, v1.w};
            uint32_t hi[4], lo[4];
#pragma unroll
            for (int p = 0; p < 4; p++) {
                __nv_bfloat16 h0 = __float2bfloat16(f[p * 2]);
                __nv_bfloat16 h1 = __float2bfloat16(f[p * 2 + 1]);
                __nv_bfloat16 l0 = __float2bfloat16(f[p * 2] - __bfloat162float(h0));
                __nv_bfloat16 l1 = __float2bfloat16(f[p * 2 + 1] - __bfloat162float(h1));
                __nv_bfloat162 ph = {h0, h1}, pl = {l0, l1};
                hi[p] = *(uint32_t*)&ph;
                lo[p] = *(uint32_t*)&pl;
            }
            uint32_t chunk = (uint32_t)(colbase >> 3) << 4;
            uint32_t off = rowoff + (chunk ^ rsw);
            asm volatile("st.shared.v4.b32 [%0], {%1,%2,%3,%4};"
                         :: "r"(sXh + off), "r"(hi[0]), "r"(hi[1]), "r"(hi[2]), "r"(hi[3]));
            asm volatile("st.shared.v4.b32 [%0], {%1,%2,%3,%4};"
                         :: "r"(sXl + off), "r"(lo[0]), "r"(lo[1]), "r"(lo[2]), "r"(lo[3]));
        }
    }

    // ---- warp tiling: warp tile 16 (m) x 64 (n) ----
    const int m0 = (wid & 3) * 16;
    const int n0 = (wid >> 2) * 64;
    const int t7 = lane & 7;
    const uint32_t dkc = (uint32_t)(lane >> 4);
    const int rsel = ((lane >> 3) & 1) * 8;
    const uint32_t aRowBase = (uint32_t)(m0 + t7 + rsel) * 256u;
    const uint32_t bRowBase = (uint32_t)(n0 + t7 + rsel) * 256u;
    const uint32_t rsw = (uint32_t)t7;
    const int gm0 = blockIdx.x * 64 + m0;

    auto copyB = [&](int r) {
        const uint4* srcH = (const uint4*)(g_Bh + (size_t)r * 8192);
        const uint4* srcL = (const uint4*)(g_Bl + (size_t)r * 8192);
#pragma unroll
        for (int j = 0; j < 8; j++) {
            int f = tid + j * 256;            // 2048 uint4
            uint32_t row = (uint32_t)(f >> 4);
            uint32_t chunk = (uint32_t)(f & 15);
            uint32_t off = row * 256u + ((chunk ^ (row & 7)) << 4);
            uint4 vh = srcH[f];
            uint4 vl = srcL[f];
            asm volatile("st.shared.v4.b32 [%0], {%1,%2,%3,%4};"
                         :: "r"(sBh + off), "r"(vh.x), "r"(vh.y), "r"(vh.z), "r"(vh.w));
            asm volatile("st.shared.v4.b32 [%0], {%1,%2,%3,%4};"
                         :: "r"(sBl + off), "r"(vl.x), "r"(vl.y), "r"(vl.z), "r"(vl.w));
        }
    };

    copyB(0);
    __syncthreads();

#pragma unroll 1
    for (int r = 0; r < RREL; r++) {
        if (r > 0) {
            __syncthreads();
            copyB(r);
            __syncthreads();
        }

        float C[8][4];
#pragma unroll
        for (int nj = 0; nj < 8; nj++)
#pragma unroll
            for (int q = 0; q < 4; q++) C[nj][q] = 0.f;

#pragma unroll
        for (int kk = 0; kk < 8; kk++) {
            uint32_t chunk = (((uint32_t)(kk * 2) + dkc) ^ rsw) << 4;
            uint32_t ah[4], al[4], bh[16], bl[16];
            ldm4(ah, sXh + aRowBase + chunk);
            ldm4(al, sXl + aRowBase + chunk);
#pragma unroll
            for (int p = 0; p < 4; p++) {
                ldm4(bh + 4 * p, sBh + bRowBase + (uint32_t)p * 4096 + chunk);
                ldm4(bl + 4 * p, sBl + bRowBase + (uint32_t)p * 4096 + chunk);
            }
#pragma unroll
            for (int p = 0; p < 4; p++) {
                mma_bf16(C[2 * p],     ah, bh[4 * p],     bh[4 * p + 2]);
                mma_bf16(C[2 * p + 1], ah, bh[4 * p + 1], bh[4 * p + 3]);
                mma_bf16(C[2 * p],     ah, bl[4 * p],     bl[4 * p + 2]);
                mma_bf16(C[2 * p + 1], ah, bl[4 * p + 1], bl[4 * p + 3]);
                mma_bf16(C[2 * p],     al, bh[4 * p],     bh[4 * p + 2]);
                mma_bf16(C[2 * p + 1], al, bh[4 * p + 1], bh[4 * p + 3]);
            }
        }

        // store C -> g_M[r]
        float* Mr = g_M + (size_t)r * NM;
        int row0 = gm0 + (lane >> 2);
        int row1 = row0 + 8;
#pragma unroll
        for (int nj = 0; nj < 8; nj++) {
            int col = n0 + nj * 8 + (lane & 3) * 2;
            if (row0 < N_NODES) {
                float2 v = {C[nj][0], C[nj][1]};
                *(float2*)(Mr + (size_t)row0 * D + col) = v;
            }
            if (row1 < N_NODES) {
                float2 v = {C[nj][2], C[nj][3]};
                *(float2*)(Mr + (size_t)row1 * D + col) = v;
            }
        }
    }
}

// ---------------------------------------------------------------------------
// Fused gather + bias + relu: one warp per node.
// out[n] = relu( sum_r sum_{e in CSR_r[n]} c_e * M_r[src_e] + bsum )
// ---------------------------------------------------------------------------
__global__ __launch_bounds__(256) void gather_kernel(float* __restrict__ out)
{
    int w = (blockIdx.x * 256 + threadIdx.x) >> 5;
    if (w >= N_NODES) return;
    int lane = threadIdx.x & 31;

    float4 acc = make_float4(0.f, 0.f, 0.f, 0.f);
#pragma unroll
    for (int r = 0; r < RREL; r++) {
        int idx = r * N_NODES + w;
        int beg = __ldg(&g_off[idx]);
        int end = __ldg(&g_off[idx + 1]);
        const float4* Mr = (const float4*)(g_M + (size_t)r * NM);
        int j = beg;
        for (; j + 1 < end; j += 2) {
            uint2 e0 = __ldg(&g_edges[j]);
            uint2 e1 = __ldg(&g_edges[j + 1]);
            float4 v0 = Mr[(size_t)e0.x * 32 + lane];
            float4 v1 = Mr[(size_t)e1.x * 32 + lane];
            float c0 = __uint_as_float(e0.y);
            float c1 = __uint_as_float(e1.y);
            acc.x += c0 * v0.x + c1 * v1.x;
            acc.y += c0 * v0.y + c1 * v1.y;
            acc.z += c0 * v0.z + c1 * v1.z;
            acc.w += c0 * v0.w + c1 * v1.w;
        }
        if (j < end) {
            uint2 e0 = __ldg(&g_edges[j]);
            float4 v0 = Mr[(size_t)e0.x * 32 + lane];
            float c0 = __uint_as_float(e0.y);
            acc.x += c0 * v0.x;
            acc.y += c0 * v0.y;
            acc.z += c0 * v0.z;
            acc.w += c0 * v0.w;
        }
    }

    float4 b = ((const float4*)g_bsum)[lane];
    float4 o;
    o.x = fmaxf(acc.x + b.x, 0.f);
    o.y = fmaxf(acc.y + b.y, 0.f);
    o.z = fmaxf(acc.z + b.z, 0.f);
    o.w = fmaxf(acc.w + b.w, 0.f);
    ((float4*)out)[(size_t)w * 32 + lane] = o;
}

// ---------------------------------------------------------------------------
// Launcher
// ---------------------------------------------------------------------------
extern "C" void kernel_launch(void* const* d_in, const int* in_sizes, int n_in,
                              void* d_out, int out_size)
{
    const float* x = nullptr;
    const float* Wp[RREL] = {nullptr, nullptr, nullptr};
    const float* bp[RREL] = {nullptr, nullptr, nullptr};
    const int*   ep[2 * RREL] = {nullptr};
    int wi = 0, bi = 0, ei = 0;

    for (int i = 0; i < n_in; i++) {
        int sz = in_sizes[i];
        if (sz == N_NODES * D)      x = (const float*)d_in[i];
        else if (sz == D * D)       { if (wi < RREL) Wp[wi++] = (const float*)d_in[i]; }
        else if (sz == D)           { if (bi < RREL) bp[bi++] = (const float*)d_in[i]; }
        else if (sz == E_EDGES)     { if (ei < 2 * RREL) ep[ei++] = (const int*)d_in[i]; }
    }

    float* out = (float*)d_out;
    const int GEMM_SMEM = 3 * 32768;  // 96KB -> 2 CTAs/SM
    cudaFuncSetAttribute(gemm_hmma_kernel,
                         cudaFuncAttributeMaxDynamicSharedMemorySize, GEMM_SMEM);

    // 1. zero degrees + cursors
    {
        int total = (2 * RREL * N_NODES) / 4 + TOT3N / 4;
        zero_kernel<<<(total + 255) / 256, 256>>>();
    }

    // 2. degrees
    {
        dim3 grid((E_EDGES + 255) / 256, RREL);
        degree_kernel<<<grid, 256>>>(ep[0], ep[1], ep[2], ep[3], ep[4], ep[5]);
    }

    // 3. convert W + bias sum
    convert_w_kernel<<<RREL, 128>>>(Wp[0], Wp[1], Wp[2], bp[0], bp[1], bp[2]);

    // 4. CSR offsets: 3-pass scan over concatenated deg_in
    const int NBLK = (TOT3N + 1023) / 1024;  // 293
    scan1_kernel<<<NBLK, 256>>>();
    scan2_kernel<<<1, 512>>>(NBLK);
    scan3_kernel<<<(TOT3N + 255) / 256, 256>>>();

    // 5. fill CSR edges
    {
        dim3 grid((E_EDGES + 255) / 256, RREL);
        fill_kernel<<<grid, 256>>>(ep[0], ep[1], ep[2], ep[3], ep[4], ep[5]);
    }

    // 6. tensor-core GEMM, all relations
    gemm_hmma_kernel<<<TILES64, 256, GEMM_SMEM>>>(x);

    // 7. fused gather + bias + relu
    {
        int blocks = (int)(((long long)N_NODES * 32 + 255) / 256);
        gather_kernel<<<blocks, 256>>>(out);
    }
}

// round 7
// speedup vs baseline: 1.7849x; 1.1084x over previous
#include <cuda_runtime.h>
#include <cuda_bf16.h>
#include <cstdint>
#include <math.h>

#define N_NODES 100000
#define D 128
#define RREL 3
#define E_EDGES 600000
#define TILES64 ((N_NODES + 63) / 64)   // 1563
#define NM ((size_t)N_NODES * D)
#define TOT3N (3 * N_NODES)

// Scratch: static device globals (no allocation allowed).
__device__ float    g_agg[RREL * NM];                  // per-relation aggregated features
__device__ float    g_deg[(size_t)2 * RREL * N_NODES]; // [2r]=deg_out_r, [2r+1]=deg_in_r
__device__ uint32_t g_Bh[RREL * 8192];                 // W_r^T bf16 hi, [n][k] (32KB/rel)
__device__ uint32_t g_Bl[RREL * 8192];                 // W_r^T bf16 lo
__device__ int      g_off[TOT3N + 1];                  // CSR offsets (concat over relations)
__device__ int      g_cursor[TOT3N];                   // fill cursors
__device__ int      g_blk[512];                        // scan block sums
__device__ uint2    g_edges[RREL * E_EDGES];           // {src, rsqrt_out[src]} CSR by dst
__device__ float    g_bsum[D];                         // b0+b1+b2

// ---------------------------------------------------------------------------
// Helpers
// ---------------------------------------------------------------------------
__device__ __forceinline__ uint32_t smem_u32(const void* p) {
    uint32_t a;
    asm("{ .reg .u64 t; cvta.to.shared.u64 t, %1; cvt.u32.u64 %0, t; }"
        : "=r"(a) : "l"(p));
    return a;
}

__device__ __forceinline__ void ldm4(uint32_t r[4], uint32_t addr) {
    asm volatile("ldmatrix.sync.aligned.m8n8.x4.shared.b16 {%0,%1,%2,%3}, [%4];"
                 : "=r"(r[0]), "=r"(r[1]), "=r"(r[2]), "=r"(r[3]) : "r"(addr));
}

__device__ __forceinline__ void mma_bf16(float c[4], const uint32_t a[4],
                                         uint32_t b0, uint32_t b1) {
    asm volatile(
        "mma.sync.aligned.m16n8k16.row.col.f32.bf16.bf16.f32 "
        "{%0,%1,%2,%3}, {%4,%5,%6,%7}, {%8,%9}, {%0,%1,%2,%3};"
        : "+f"(c[0]), "+f"(c[1]), "+f"(c[2]), "+f"(c[3])
        : "r"(a[0]), "r"(a[1]), "r"(a[2]), "r"(a[3]), "r"(b0), "r"(b1));
}

// streaming (evict-first) float4 store
__device__ __forceinline__ void stcs4(float* p, float4 v) {
    asm volatile("st.global.cs.v4.f32 [%0], {%1,%2,%3,%4};"
                 :: "l"(p), "f"(v.x), "f"(v.y), "f"(v.z), "f"(v.w) : "memory");
}

// ---------------------------------------------------------------------------
// Zero: degrees (600000 floats) + cursors (300000 ints)
// ---------------------------------------------------------------------------
__global__ __launch_bounds__(256) void zero_kernel() {
    const int nf4 = (2 * RREL * N_NODES) / 4;   // 150000
    const int ni4 = TOT3N / 4;                  // 75000
    int i = blockIdx.x * 256 + threadIdx.x;
    if (i < nf4) {
        ((float4*)g_deg)[i] = make_float4(0.f, 0.f, 0.f, 0.f);
    } else {
        int j = i - nf4;
        if (j < ni4) ((int4*)g_cursor)[j] = make_int4(0, 0, 0, 0);
    }
}

// ---------------------------------------------------------------------------
// Degree counting
// ---------------------------------------------------------------------------
__global__ __launch_bounds__(256) void degree_kernel(
    const int* __restrict__ s0, const int* __restrict__ d0,
    const int* __restrict__ s1, const int* __restrict__ d1,
    const int* __restrict__ s2, const int* __restrict__ d2)
{
    int e = blockIdx.x * 256 + threadIdx.x;
    if (e >= E_EDGES) return;
    int r = blockIdx.y;
    const int* sp = (r == 0) ? s0 : ((r == 1) ? s1 : s2);
    const int* dp = (r == 0) ? d0 : ((r == 1) ? d1 : d2);
    atomicAdd(&g_deg[(size_t)(2 * r) * N_NODES + sp[e]], 1.0f);
    atomicAdd(&g_deg[(size_t)(2 * r + 1) * N_NODES + dp[e]], 1.0f);
}

// ---------------------------------------------------------------------------
// Convert W_r -> transposed bf16 hi/lo, row-major [n][k]; also bias sum.
// ---------------------------------------------------------------------------
__global__ __launch_bounds__(128) void convert_w_kernel(
    const float* __restrict__ W0, const float* __restrict__ W1,
    const float* __restrict__ W2,
    const float* __restrict__ b0, const float* __restrict__ b1,
    const float* __restrict__ b2)
{
    int r = blockIdx.x;
    const float* W = (r == 0) ? W0 : ((r == 1) ? W1 : W2);
    int n = threadIdx.x;
    if (r == 0) g_bsum[n] = b0[n] + b1[n] + b2[n];
    __nv_bfloat16* bh = (__nv_bfloat16*)(g_Bh + (size_t)r * 8192);
    __nv_bfloat16* bl = (__nv_bfloat16*)(g_Bl + (size_t)r * 8192);
#pragma unroll 4
    for (int k = 0; k < D; k++) {
        float w = W[(size_t)k * D + n];
        __nv_bfloat16 h = __float2bfloat16(w);
        __nv_bfloat16 l = __float2bfloat16(w - __bfloat162float(h));
        bh[n * D + k] = h;
        bl[n * D + k] = l;
    }
}

// ---------------------------------------------------------------------------
// Scan pass 1: per-block (1024 elems) exclusive scan of concatenated deg_in
// ---------------------------------------------------------------------------
__global__ __launch_bounds__(256) void scan1_kernel() {
    __shared__ int warpsum[8];
    int tid = threadIdx.x;
    int base = blockIdx.x * 1024 + tid * 4;
    int v[4];
#pragma unroll
    for (int j = 0; j < 4; j++) {
        int idx = base + j;
        int val = 0;
        if (idx < TOT3N) {
            int r = idx / N_NODES;
            int i = idx - r * N_NODES;
            val = (int)(g_deg[(size_t)(2 * r + 1) * N_NODES + i] + 0.5f);
        }
        v[j] = val;
    }
    int s = v[0] + v[1] + v[2] + v[3];
    int lane = tid & 31, wid = tid >> 5;
    int inc = s;
#pragma unroll
    for (int dlt = 1; dlt < 32; dlt <<= 1) {
        int t = __shfl_up_sync(0xffffffffu, inc, dlt);
        if (lane >= dlt) inc += t;
    }
    if (lane == 31) warpsum[wid] = inc;
    __syncthreads();
    if (wid == 0) {
        int ws = (lane < 8) ? warpsum[lane] : 0;
#pragma unroll
        for (int dlt = 1; dlt < 8; dlt <<= 1) {
            int t = __shfl_up_sync(0xffffffffu, ws, dlt);
            if (lane >= dlt) ws += t;
        }
        if (lane < 8) warpsum[lane] = ws;
    }
    __syncthreads();
    int warpbase = (wid > 0) ? warpsum[wid - 1] : 0;
    int run = warpbase + inc - s;
#pragma unroll
    for (int j = 0; j < 4; j++) {
        int idx = base + j;
        if (idx < TOT3N) g_off[idx] = run;
        run += v[j];
    }
    if (tid == 255) g_blk[blockIdx.x] = warpsum[7];
}

// ---------------------------------------------------------------------------
// Scan pass 2: exclusive scan of block sums (nblk <= 512), single block
// ---------------------------------------------------------------------------
__global__ __launch_bounds__(512) void scan2_kernel(int nblk) {
    __shared__ int sh[512];
    int tid = threadIdx.x;
    sh[tid] = (tid < nblk) ? g_blk[tid] : 0;
    __syncthreads();
#pragma unroll
    for (int dlt = 1; dlt < 512; dlt <<= 1) {
        int t = (tid >= dlt) ? sh[tid - dlt] : 0;
        __syncthreads();
        sh[tid] += t;
        __syncthreads();
    }
    if (tid < nblk) g_blk[tid] = (tid > 0) ? sh[tid - 1] : 0;
    if (tid == 0) g_off[TOT3N] = sh[511];
}

// ---------------------------------------------------------------------------
// Scan pass 3: add block offsets
// ---------------------------------------------------------------------------
__global__ __launch_bounds__(256) void scan3_kernel() {
    int i = blockIdx.x * 256 + threadIdx.x;
    if (i < TOT3N) g_off[i] += g_blk[i >> 10];
}

// ---------------------------------------------------------------------------
// Fill CSR edge lists: g_edges[pos] = {src, rsqrt_out_r[src]}, key (rel,dst)
// ---------------------------------------------------------------------------
__global__ __launch_bounds__(256) void fill_kernel(
    const int* __restrict__ s0, const int* __restrict__ d0,
    const int* __restrict__ s1, const int* __restrict__ d1,
    const int* __restrict__ s2, const int* __restrict__ d2)
{
    int e = blockIdx.x * 256 + threadIdx.x;
    if (e >= E_EDGES) return;
    int r = blockIdx.y;
    const int* sp = (r == 0) ? s0 : ((r == 1) ? s1 : s2);
    const int* dp = (r == 0) ? d0 : ((r == 1) ? d1 : d2);
    int s = __ldg(sp + e);
    int d = __ldg(dp + e);
    float dout = g_deg[(size_t)(2 * r) * N_NODES + s];
    float c = rsqrtf(fmaxf(dout, 1.0f));
    int idx = r * N_NODES + d;
    int pos = g_off[idx] + atomicAdd(&g_cursor[idx], 1);
    g_edges[pos] = make_uint2((uint32_t)s, __float_as_uint(c));
}

// ---------------------------------------------------------------------------
// Gather over raw x (L2-resident 51MB): one warp per node.
// agg_r[d] = rsqrt_in_r[d] * sum_e rsqrt_out_r[src_e] * x[src_e]
// ---------------------------------------------------------------------------
__global__ __launch_bounds__(256) void gather_kernel(const float* __restrict__ X)
{
    int w = (blockIdx.x * 256 + threadIdx.x) >> 5;
    if (w >= N_NODES) return;
    int lane = threadIdx.x & 31;
    const float4* x4 = (const float4*)X;

#pragma unroll
    for (int r = 0; r < RREL; r++) {
        int idx = r * N_NODES + w;
        int beg = __ldg(&g_off[idx]);
        int end = __ldg(&g_off[idx + 1]);
        float4 acc = make_float4(0.f, 0.f, 0.f, 0.f);
        int j = beg;
        for (; j + 1 < end; j += 2) {
            uint2 e0 = __ldg(&g_edges[j]);
            uint2 e1 = __ldg(&g_edges[j + 1]);
            float4 v0 = x4[(size_t)e0.x * 32 + lane];
            float4 v1 = x4[(size_t)e1.x * 32 + lane];
            float c0 = __uint_as_float(e0.y);
            float c1 = __uint_as_float(e1.y);
            acc.x += c0 * v0.x + c1 * v1.x;
            acc.y += c0 * v0.y + c1 * v1.y;
            acc.z += c0 * v0.z + c1 * v1.z;
            acc.w += c0 * v0.w + c1 * v1.w;
        }
        if (j < end) {
            uint2 e0 = __ldg(&g_edges[j]);
            float4 v0 = x4[(size_t)e0.x * 32 + lane];
            float c0 = __uint_as_float(e0.y);
            acc.x += c0 * v0.x;
            acc.y += c0 * v0.y;
            acc.z += c0 * v0.z;
            acc.w += c0 * v0.w;
        }
        float din = g_deg[(size_t)(2 * r + 1) * N_NODES + w];
        float ci = rsqrtf(fmaxf(din, 1.0f));
        acc.x *= ci; acc.y *= ci; acc.z *= ci; acc.w *= ci;
        // streaming store: don't evict x from L2
        stcs4(g_agg + (size_t)r * NM + (size_t)w * D + lane * 4, acc);
    }
}

// ---------------------------------------------------------------------------
// HMMA GEMM (K=384): out = relu( sum_r agg_r @ W_r^T-ish + bsum )
// CTA = 64 rows x 128 cols, 256 threads (8 warps, warp tile 16x64), 96KB smem
// -> 2 CTAs/SM. Per relation: convert agg_r tile to bf16 hi/lo swizzled smem,
// copy B_r, 8 k-steps of split-bf16 MMA, accumulating C across relations.
// ---------------------------------------------------------------------------
__global__ __launch_bounds__(256, 2) void gemm_hmma_kernel(float* __restrict__ out)
{
    extern __shared__ char sm[];
    uint32_t sbase = smem_u32(sm);
    const uint32_t sXh = sbase;             // 16KB (64 rows x 256B)
    const uint32_t sXl = sbase + 16384;
    const uint32_t sBh = sbase + 32768;     // 32KB (128 rows x 256B)
    const uint32_t sBl = sbase + 65536;

    const int tid = threadIdx.x;
    const int wid = tid >> 5;
    const int lane = tid & 31;

    // ---- warp tiling: warp tile 16 (m) x 64 (n) ----
    const int m0 = (wid & 3) * 16;
    const int n0 = (wid >> 2) * 64;
    const int t7 = lane & 7;
    const uint32_t dkc = (uint32_t)(lane >> 4);
    const int rsel = ((lane >> 3) & 1) * 8;
    const uint32_t aRowBase = (uint32_t)(m0 + t7 + rsel) * 256u;
    const uint32_t bRowBase = (uint32_t)(n0 + t7 + rsel) * 256u;
    const uint32_t rsw = (uint32_t)t7;
    const int gm0 = blockIdx.x * 64 + m0;

    // A-load/convert params
    const int arow = tid >> 2;                 // 0..63
    const int aq = tid & 3;                    // 32-col quarter
    const int agrow = blockIdx.x * 64 + arow;
    const bool avalid = agrow < N_NODES;
    const uint32_t arowoff = (uint32_t)arow * 256u;
    const uint32_t arsw = (uint32_t)(arow & 7) << 4;

    float C[8][4];
#pragma unroll
    for (int nj = 0; nj < 8; nj++)
#pragma unroll
        for (int q = 0; q < 4; q++) C[nj][q] = 0.f;

#pragma unroll 1
    for (int r = 0; r < RREL; r++) {
        if (r > 0) __syncthreads();  // prior MMA smem reads complete

        // ---- convert agg_r rows into swizzled bf16 hi/lo smem ----
        {
            const float4* xr = (const float4*)(g_agg + (size_t)r * NM
                                               + (size_t)(avalid ? agrow : 0) * D);
#pragma unroll
            for (int i = 0; i < 4; i++) {
                int colbase = aq * 32 + i * 8;
                float4 v0 = make_float4(0.f, 0.f, 0.f, 0.f), v1 = v0;
                if (avalid) {
                    v0 = xr[colbase / 4];
                    v1 = xr[colbase / 4 + 1];
                }
                float f[8] = {v0.x, v0.y, v0.z, v0.w, v1.x, v1.y, v1.z, v1.w};
                uint32_t hi[4], lo[4];
#pragma unroll
                for (int p = 0; p < 4; p++) {
                    __nv_bfloat16 h0 = __float2bfloat16(f[p * 2]);
                    __nv_bfloat16 h1 = __float2bfloat16(f[p * 2 + 1]);
                    __nv_bfloat16 l0 = __float2bfloat16(f[p * 2] - __bfloat162float(h0));
                    __nv_bfloat16 l1 = __float2bfloat16(f[p * 2 + 1] - __bfloat162float(h1));
                    __nv_bfloat162 ph = {h0, h1}, pl = {l0, l1};
                    hi[p] = *(uint32_t*)&ph;
                    lo[p] = *(uint32_t*)&pl;
                }
                uint32_t chunk = (uint32_t)(colbase >> 3) << 4;
                uint32_t off = arowoff + (chunk ^ arsw);
                asm volatile("st.shared.v4.b32 [%0], {%1,%2,%3,%4};"
                             :: "r"(sXh + off), "r"(hi[0]), "r"(hi[1]), "r"(hi[2]), "r"(hi[3]));
                asm volatile("st.shared.v4.b32 [%0], {%1,%2,%3,%4};"
                             :: "r"(sXl + off), "r"(lo[0]), "r"(lo[1]), "r"(lo[2]), "r"(lo[3]));
            }
        }

        // ---- copy B_r (swizzled) ----
        {
            const uint4* srcH = (const uint4*)(g_Bh + (size_t)r * 8192);
            const uint4* srcL = (const uint4*)(g_Bl + (size_t)r * 8192);
#pragma unroll
            for (int j = 0; j < 8; j++) {
                int f = tid + j * 256;            // 2048 uint4
                uint32_t row = (uint32_t)(f >> 4);
                uint32_t chunk = (uint32_t)(f & 15);
                uint32_t off = row * 256u + ((chunk ^ (row & 7)) << 4);
                uint4 vh = srcH[f];
                uint4 vl = srcL[f];
                asm volatile("st.shared.v4.b32 [%0], {%1,%2,%3,%4};"
                             :: "r"(sBh + off), "r"(vh.x), "r"(vh.y), "r"(vh.z), "r"(vh.w));
                asm volatile("st.shared.v4.b32 [%0], {%1,%2,%3,%4};"
                             :: "r"(sBl + off), "r"(vl.x), "r"(vl.y), "r"(vl.z), "r"(vl.w));
            }
        }
        __syncthreads();

#pragma unroll
        for (int kk = 0; kk < 8; kk++) {
            uint32_t chunk = (((uint32_t)(kk * 2) + dkc) ^ rsw) << 4;
            uint32_t ah[4], al[4], bh[16], bl[16];
            ldm4(ah, sXh + aRowBase + chunk);
            ldm4(al, sXl + aRowBase + chunk);
#pragma unroll
            for (int p = 0; p < 4; p++) {
                ldm4(bh + 4 * p, sBh + bRowBase + (uint32_t)p * 4096 + chunk);
                ldm4(bl + 4 * p, sBl + bRowBase + (uint32_t)p * 4096 + chunk);
            }
#pragma unroll
            for (int p = 0; p < 4; p++) {
                mma_bf16(C[2 * p],     ah, bh[4 * p],     bh[4 * p + 2]);
                mma_bf16(C[2 * p + 1], ah, bh[4 * p + 1], bh[4 * p + 3]);
                mma_bf16(C[2 * p],     ah, bl[4 * p],     bl[4 * p + 2]);
                mma_bf16(C[2 * p + 1], ah, bl[4 * p + 1], bl[4 * p + 3]);
                mma_bf16(C[2 * p],     al, bh[4 * p],     bh[4 * p + 2]);
                mma_bf16(C[2 * p + 1], al, bh[4 * p + 1], bh[4 * p + 3]);
            }
        }
    }

    // ---- epilogue: bias + relu -> out ----
    int row0 = gm0 + (lane >> 2);
    int row1 = row0 + 8;
#pragma unroll
    for (int nj = 0; nj < 8; nj++) {
        int col = n0 + nj * 8 + (lane & 3) * 2;
        float b0v = g_bsum[col], b1v = g_bsum[col + 1];
        if (row0 < N_NODES) {
            float2 v = {fmaxf(C[nj][0] + b0v, 0.f), fmaxf(C[nj][1] + b1v, 0.f)};
            *(float2*)(out + (size_t)row0 * D + col) = v;
        }
        if (row1 < N_NODES) {
            float2 v = {fmaxf(C[nj][2] + b0v, 0.f), fmaxf(C[nj][3] + b1v, 0.f)};
            *(float2*)(out + (size_t)row1 * D + col) = v;
        }
    }
}

// ---------------------------------------------------------------------------
// Launcher
// ---------------------------------------------------------------------------
extern "C" void kernel_launch(void* const* d_in, const int* in_sizes, int n_in,
                              void* d_out, int out_size)
{
    const float* x = nullptr;
    const float* Wp[RREL] = {nullptr, nullptr, nullptr};
    const float* bp[RREL] = {nullptr, nullptr, nullptr};
    const int*   ep[2 * RREL] = {nullptr};
    int wi = 0, bi = 0, ei = 0;

    for (int i = 0; i < n_in; i++) {
        int sz = in_sizes[i];
        if (sz == N_NODES * D)      x = (const float*)d_in[i];
        else if (sz == D * D)       { if (wi < RREL) Wp[wi++] = (const float*)d_in[i]; }
        else if (sz == D)           { if (bi < RREL) bp[bi++] = (const float*)d_in[i]; }
        else if (sz == E_EDGES)     { if (ei < 2 * RREL) ep[ei++] = (const int*)d_in[i]; }
    }

    float* out = (float*)d_out;
    const int GEMM_SMEM = 3 * 32768;  // 96KB -> 2 CTAs/SM
    cudaFuncSetAttribute(gemm_hmma_kernel,
                         cudaFuncAttributeMaxDynamicSharedMemorySize, GEMM_SMEM);

    // 1. zero degrees + cursors
    {
        int total = (2 * RREL * N_NODES) / 4 + TOT3N / 4;
        zero_kernel<<<(total + 255) / 256, 256>>>();
    }

    // 2. degrees
    {
        dim3 grid((E_EDGES + 255) / 256, RREL);
        degree_kernel<<<grid, 256>>>(ep[0], ep[1], ep[2], ep[3], ep[4], ep[5]);
    }

    // 3. convert W + bias sum
    convert_w_kernel<<<RREL, 128>>>(Wp[0], Wp[1], Wp[2], bp[0], bp[1], bp[2]);

    // 4. CSR offsets: 3-pass scan over concatenated deg_in
    const int NBLK = (TOT3N + 1023) / 1024;  // 293
    scan1_kernel<<<NBLK, 256>>>();
    scan2_kernel<<<1, 512>>>(NBLK);
    scan3_kernel<<<(TOT3N + 255) / 256, 256>>>();

    // 5. fill CSR edges
    {
        dim3 grid((E_EDGES + 255) / 256, RREL);
        fill_kernel<<<grid, 256>>>(ep[0], ep[1], ep[2], ep[3], ep[4], ep[5]);
    }

    // 6. gather over x (L2-resident) -> agg_r
    {
        int blocks = (int)(((long long)N_NODES * 32 + 255) / 256);
        gather_kernel<<<blocks, 256>>>(x);
    }

    // 7. fused K=384 GEMM + bias + relu -> out
    gemm_hmma_kernel<<<TILES64, 256, GEMM_SMEM>>>(out);
}